// round 5
// baseline (speedup 1.0000x reference)
#include <cuda_runtime.h>

// FusionMarkovGNN — algebraically collapsed.
//   W_eff[n,l] = conv_w[l] @ mss[n] = wsum_l @ relu(adj_n) + rare exact
//   corrections (full/zero sign-pattern columns, gathered into a list).
//   Per layer: y = relu(BN(W_eff[n,l] @ x + conv_b)).
// GEMMs: 64x128 tiles, 512 threads (16 warps), packed fp32 fma.rn.f32x2,
// A tile stored pre-duplicated in smem (zero dup MOVs in inner loop),
// global loads software-pipelined one k-chunk ahead.

#define CC 256
#define SS 16
#define HW 1024
#define NB 4

typedef unsigned long long u64;

__device__ float g_wsum[3 * CC * CC];       // [l][o][a]
__device__ float g_weff[NB * 3 * CC * CC];  // [n][l][o][b]
__device__ int   g_ncorr;
__device__ int   g_corr[NB * SS * CC];

// ---------------------------------------------------------------- f32x2 helpers
__device__ __forceinline__ void ffma2(u64& d, u64 a, u64 b) {
    asm("fma.rn.f32x2 %0, %1, %2, %0;" : "+l"(d) : "l"(a), "l"(b));
}
__device__ __forceinline__ u64 dupf(float x) {
    u64 r; asm("mov.b64 %0, {%1, %1};" : "=l"(r) : "f"(x)); return r;
}
__device__ __forceinline__ float2 unpk(u64 v) {
    float2 r; asm("mov.b64 {%0, %1}, %2;" : "=f"(r.x), "=f"(r.y) : "l"(v)); return r;
}

// ---------------------------------------------------------------- reset
__global__ void reset_kernel() { g_ncorr = 0; }

// ---------------------------------------------------------------- detect exceptions
// state 1 = full (all 16 rows > 0), state 2 = zero (none > 0)
__global__ void detect_kernel(const float* __restrict__ adj) {
    int n = blockIdx.x, k = blockIdx.y, b = threadIdx.x;
    const float* m = adj + n * CC * CC;
    bool anyp = false, allp = true;
#pragma unroll
    for (int i = 0; i < 16; i++) {
        float v = m[(k * 16 + i) * CC + b];
        anyp = anyp || (v > 0.0f);
        allp = allp && (v > 0.0f);
    }
    if (allp || !anyp) {
        int idx = atomicAdd(&g_ncorr, 1);
        g_corr[idx] = (n << 16) | (k << 10) | (b << 2) | (allp ? 1 : 2);
    }
}

// ---------------------------------------------------------------- wsum
// wsum[l][o][a] = sum_k conv_w[l][o][k*256 + a]
__global__ void wsum_kernel(const float* __restrict__ w) {
    int idx = blockIdx.x * 256 + threadIdx.x;
    int l  = idx >> 16;
    int oa = idx & 0xFFFF;
    int o = oa >> 8, a = oa & 255;
    const float* base = w + (size_t)l * CC * SS * CC + (size_t)o * (SS * CC) + a;
    float s = 0.0f;
#pragma unroll
    for (int k = 0; k < 16; k++) s += base[k * CC];
    g_wsum[idx] = s;
}

// ---------------------------------------------------------------- GEMM core
// 64x128 output tile, 512 threads, micro 4 rows x 4 cols (2 f32x2 pairs).
// Ad: A chunk duplicated per element as (a,a) u64; row padded to 66.
// Global loads for chunk k+1 issued before the compute of chunk k.
template <int BSTRIDE, bool RELU_B>
__device__ __forceinline__ void gemm_tile(
    const float* __restrict__ A, const float* __restrict__ B,
    int row0, int col0, u64 (&acc)[4][2],
    u64 (*Ad)[66], float (*Bs)[128]) {
    int tid = threadIdx.x;
    int ar = tid >> 3, ac = tid & 7;            // A: 64 rows x 8 float2
    int brow = tid >> 5, bcol = (tid & 31) * 4; // B: 16 rows x 32 float4
    int tr = tid >> 5, tc = tid & 31;           // compute: warp = row group

    const float* Aptr = A + (row0 + ar) * CC + ac * 2;
    const float* Bptr = B + brow * BSTRIDE + col0 + bcol;

    float2 a2 = *(const float2*)(Aptr);
    float4 b4 = *(const float4*)(Bptr);

    for (int k0 = 0; k0 < CC; k0 += 16) {
        Ad[ac * 2 + 0][ar] = dupf(a2.x);
        Ad[ac * 2 + 1][ar] = dupf(a2.y);
        if (RELU_B) {
            b4.x = fmaxf(b4.x, 0.0f); b4.y = fmaxf(b4.y, 0.0f);
            b4.z = fmaxf(b4.z, 0.0f); b4.w = fmaxf(b4.w, 0.0f);
        }
        *(float4*)&Bs[brow][bcol] = b4;
        __syncthreads();
        if (k0 + 16 < CC) {                     // prefetch next chunk
            a2 = *(const float2*)(Aptr + k0 + 16);
            b4 = *(const float4*)(Bptr + (size_t)(k0 + 16) * BSTRIDE);
        }
#pragma unroll
        for (int k = 0; k < 16; k++) {
            ulonglong2 a01 = *(const ulonglong2*)&Ad[k][tr * 4];
            ulonglong2 a23 = *(const ulonglong2*)&Ad[k][tr * 4 + 2];
            ulonglong2 b   = *(const ulonglong2*)&Bs[k][tc * 4];
            ffma2(acc[0][0], a01.x, b.x); ffma2(acc[0][1], a01.x, b.y);
            ffma2(acc[1][0], a01.y, b.x); ffma2(acc[1][1], a01.y, b.y);
            ffma2(acc[2][0], a23.x, b.x); ffma2(acc[2][1], a23.x, b.y);
            ffma2(acc[3][0], a23.y, b.x); ffma2(acc[3][1], a23.y, b.y);
        }
        __syncthreads();
    }
}

// ---------------------------------------------------------------- W_eff GEMM
// g_weff[n][l] = wsum[l] @ relu(adj[n]); grid (2, 4, 12), 512 threads.
__global__ __launch_bounds__(512) void weff_kernel(const float* __restrict__ adj) {
    __shared__ u64 Ad[16][66];
    __shared__ float Bs[16][128];
    int nl = blockIdx.z;
    const float* A = g_wsum + (size_t)(nl % 3) * (CC * CC);
    const float* B = adj    + (size_t)(nl / 3) * (CC * CC);
    float* Cc = g_weff + (size_t)nl * (CC * CC);
    int row0 = blockIdx.y * 64, col0 = blockIdx.x * 128;
    int tr = threadIdx.x >> 5, tc = threadIdx.x & 31;

    u64 acc[4][2] = {};
    gemm_tile<CC, true>(A, B, row0, col0, acc, Ad, Bs);

#pragma unroll
    for (int i = 0; i < 4; i++) {
        int o = row0 + tr * 4 + i;
        float2 p0 = unpk(acc[i][0]), p1 = unpk(acc[i][1]);
        float4 v = {p0.x, p0.y, p1.x, p1.y};
        *(float4*)(Cc + o * CC + col0 + tc * 4) = v;
    }
}

// ---------------------------------------------------------------- corrections
__global__ __launch_bounds__(256) void corr2_kernel(const float* __restrict__ adj,
                                                    const float* __restrict__ w) {
    int l = blockIdx.x;
    int o = threadIdx.x;
    __shared__ float mcol[CC];
    int ncorr = g_ncorr;
    for (int e = 0; e < ncorr; e++) {
        int ent = g_corr[e];
        int n = ent >> 16, k = (ent >> 10) & 0x3F, b = (ent >> 2) & 0xFF, st = ent & 3;
        __syncthreads();
        mcol[o] = adj[(size_t)n * CC * CC + o * CC + b];
        __syncthreads();
        const float* wrow = w + (size_t)l * CC * SS * CC + (size_t)o * (SS * CC) + k * CC;
        float s = 0.0f;
        if (st == 1) {
            for (int a = 0; a < CC; a++) s = fmaf(wrow[a], fminf(mcol[a], 0.0f), s);
        } else {
            for (int a = 0; a < CC; a++) s = fmaf(-wrow[a], fmaxf(mcol[a], 0.0f), s);
        }
        atomicAdd(&g_weff[(size_t)(n * 3 + l) * CC * CC + o * CC + b], s);
    }
}

// ---------------------------------------------------------------- layer GEMM + BN + ReLU
// grid (8, 4, 4), 512 threads.
__global__ __launch_bounds__(512) void layer_kernel(
    const float* __restrict__ x,
    float* __restrict__ y,
    int l,
    const float* __restrict__ cb,
    const float* __restrict__ gamma,
    const float* __restrict__ beta,
    const float* __restrict__ mean,
    const float* __restrict__ var) {
    __shared__ u64 Ad[16][66];
    __shared__ float Bs[16][128];
    int n = blockIdx.z;
    const float* A = g_weff + (size_t)(n * 3 + l) * (CC * CC);
    const float* B = x + (size_t)n * (CC * HW);
    float* Cc = y + (size_t)n * (CC * HW);
    int row0 = blockIdx.y * 64, col0 = blockIdx.x * 128;
    int tr = threadIdx.x >> 5, tc = threadIdx.x & 31;

    u64 acc[4][2] = {};
    gemm_tile<HW, false>(A, B, row0, col0, acc, Ad, Bs);

#pragma unroll
    for (int i = 0; i < 4; i++) {
        int o = row0 + tr * 4 + i;
        float sc  = gamma[o] * rsqrtf(var[o] + 1e-5f);
        float add = (cb[o] - mean[o]) * sc + beta[o];
        float2 p0 = unpk(acc[i][0]), p1 = unpk(acc[i][1]);
        float4 v;
        v.x = fmaxf(fmaf(p0.x, sc, add), 0.0f);
        v.y = fmaxf(fmaf(p0.y, sc, add), 0.0f);
        v.z = fmaxf(fmaf(p1.x, sc, add), 0.0f);
        v.w = fmaxf(fmaf(p1.y, sc, add), 0.0f);
        *(float4*)(Cc + o * HW + col0 + tc * 4) = v;
    }
}

// ---------------------------------------------------------------- launch
extern "C" void kernel_launch(void* const* d_in, const int* in_sizes, int n_in,
                              void* d_out, int out_size) {
    (void)in_sizes; (void)n_in; (void)out_size;
    const float* feats = (const float*)d_in[0];  // [4,256,32,32]
    const float* adj   = (const float*)d_in[1];  // [4,256,256]
    const float* convw = (const float*)d_in[2];  // [3,256,4096]
    const float* convb = (const float*)d_in[3];  // [3,256]
    const float* gamma = (const float*)d_in[4];
    const float* beta  = (const float*)d_in[5];
    const float* mean  = (const float*)d_in[6];
    const float* var   = (const float*)d_in[7];
    float* out = (float*)d_out;                  // [3,4,256,32,32]

    reset_kernel<<<1, 1>>>();
    detect_kernel<<<dim3(NB, SS), 256>>>(adj);
    wsum_kernel<<<768, 256>>>(convw);
    weff_kernel<<<dim3(2, 4, NB * 3), 512>>>(adj);
    corr2_kernel<<<3, 256>>>(adj, convw);

    const size_t SEC = (size_t)NB * CC * HW;
    for (int l = 0; l < 3; l++) {
        const float* x = (l == 0) ? feats : (out + (size_t)(l - 1) * SEC);
        layer_kernel<<<dim3(8, 4, NB), 512>>>(
            x, out + (size_t)l * SEC, l,
            convb + l * CC, gamma + l * CC, beta + l * CC,
            mean + l * CC, var + l * CC);
    }
}

// round 6
// speedup vs baseline: 1.1672x; 1.1672x over previous
#include <cuda_runtime.h>

// FusionMarkovGNN — algebraically collapsed.
//   W_eff[n,l] = conv_w[l] @ mss[n] = wsum_l @ relu(adj_n) + rare exact
//   corrections. Per layer: y = relu(BN(W_eff[n,l] @ x + conv_b)).
// GEMM core: 64x128 tile, 512 threads, f32x2 FFMA with ROW-PAIR packed
// accumulators (A = natural u64 pairs, broadcast LDS; B = scalar float2 +
// in-register dup), double-buffered smem chunks + register frag pipelining.

#define CC 256
#define SS 16
#define HW 1024
#define NB 4
#define ASTR 68   // As row stride (floats): 16B-aligned rows, bank-spread

typedef unsigned long long u64;

__device__ float g_wsum[3 * CC * CC];       // [l][o][a]
__device__ float g_weff[NB * 3 * CC * CC];  // [n][l][o][b]
__device__ int   g_ncorr;
__device__ int   g_corr[NB * SS * CC];

// ---------------------------------------------------------------- f32x2 helpers
__device__ __forceinline__ void ffma2(u64& d, u64 a, u64 b) {
    asm("fma.rn.f32x2 %0, %1, %2, %0;" : "+l"(d) : "l"(a), "l"(b));
}
__device__ __forceinline__ u64 dupf(float x) {
    u64 r; asm("mov.b64 %0, {%1, %1};" : "=l"(r) : "f"(x)); return r;
}
__device__ __forceinline__ float2 unpk(u64 v) {
    float2 r; asm("mov.b64 {%0, %1}, %2;" : "=f"(r.x), "=f"(r.y) : "l"(v)); return r;
}

// ---------------------------------------------------------------- reset
__global__ void reset_kernel() { g_ncorr = 0; }

// ---------------------------------------------------------------- detect exceptions
__global__ void detect_kernel(const float* __restrict__ adj) {
    int n = blockIdx.x, k = blockIdx.y, b = threadIdx.x;
    const float* m = adj + n * CC * CC;
    bool anyp = false, allp = true;
#pragma unroll
    for (int i = 0; i < 16; i++) {
        float v = m[(k * 16 + i) * CC + b];
        anyp = anyp || (v > 0.0f);
        allp = allp && (v > 0.0f);
    }
    if (allp || !anyp) {
        int idx = atomicAdd(&g_ncorr, 1);
        g_corr[idx] = (n << 16) | (k << 10) | (b << 2) | (allp ? 1 : 2);
    }
}

// ---------------------------------------------------------------- wsum
__global__ void wsum_kernel(const float* __restrict__ w) {
    int idx = blockIdx.x * 256 + threadIdx.x;
    int l  = idx >> 16;
    int oa = idx & 0xFFFF;
    int o = oa >> 8, a = oa & 255;
    const float* base = w + (size_t)l * CC * SS * CC + (size_t)o * (SS * CC) + a;
    float s = 0.0f;
#pragma unroll
    for (int k = 0; k < 16; k++) s += base[k * CC];
    g_wsum[idx] = s;
}

// ---------------------------------------------------------------- GEMM core
// 64 rows x 128 cols per block, 512 threads.
// warp: wr = wid>>1 -> rows wr*8..+7 ; wc = wid&1 -> cols wc*64 + lane*2 (+c)
// acc[rp][c]: rp = row-pair (2 rows packed in f32x2), c = 0..1.
template <int BSTRIDE, bool RELU_B>
__device__ __forceinline__ void gemm_tile(
    const float* __restrict__ A, const float* __restrict__ B,
    int row0, int col0, u64 (&acc)[4][2],
    float* As /*[2][16][ASTR]*/, float* Bs /*[2][16][128]*/) {
    int tid = threadIdx.x;
    int wid = tid >> 5, lane = tid & 31;
    int wr = wid >> 1, wc = wid & 1;

    // staging indices
    int arow = tid >> 3, akp = tid & 7;          // A: 64 rows x 8 float2 (k-pairs)
    int brow = tid >> 5, bcol = (tid & 31) * 4;  // B: 16 rows x 32 float4

    const float* Ag = A + (row0 + arow) * CC + akp * 2;
    const float* Bg = B + brow * BSTRIDE + col0 + bcol;

    // compute read offsets (word indices)
    int aoff = wr * 8;
    int boff = wc * 64 + lane * 2;

    float2 ga = *(const float2*)(Ag);
    float4 gb = *(const float4*)(Bg);

    // store chunk 0 into buffer 0
    {
        float* Ab = As;               // buf 0
        float* Bb = Bs;
        Ab[(akp * 2 + 0) * ASTR + arow] = ga.x;
        Ab[(akp * 2 + 1) * ASTR + arow] = ga.y;
        if (RELU_B) {
            gb.x = fmaxf(gb.x, 0.0f); gb.y = fmaxf(gb.y, 0.0f);
            gb.z = fmaxf(gb.z, 0.0f); gb.w = fmaxf(gb.w, 0.0f);
        }
        *(float4*)&Bb[brow * 128 + bcol] = gb;
    }
    __syncthreads();

    for (int c = 0; c < 16; c++) {
        int buf = c & 1;
        const float* Ab = As + buf * 16 * ASTR;
        const float* Bb = Bs + buf * 16 * 128;

        if (c < 15) {   // global prefetch for next chunk
            ga = *(const float2*)(Ag + (c + 1) * 16);
            gb = *(const float4*)(Bg + (size_t)(c + 1) * 16 * BSTRIDE);
        }

        // register-pipelined 16-k compute
        ulonglong2 fa0[2], fa1[2];
        float2 fb[2];
        fa0[0] = *(const ulonglong2*)&Ab[0 * ASTR + aoff];
        fa1[0] = *(const ulonglong2*)&Ab[0 * ASTR + aoff + 4];
        fb[0]  = *(const float2*)&Bb[0 * 128 + boff];
#pragma unroll
        for (int k = 0; k < 16; k++) {
            int cur = k & 1, nxt = cur ^ 1;
            if (k < 15) {
                fa0[nxt] = *(const ulonglong2*)&Ab[(k + 1) * ASTR + aoff];
                fa1[nxt] = *(const ulonglong2*)&Ab[(k + 1) * ASTR + aoff + 4];
                fb[nxt]  = *(const float2*)&Bb[(k + 1) * 128 + boff];
            }
            u64 b0 = dupf(fb[cur].x), b1 = dupf(fb[cur].y);
            ffma2(acc[0][0], fa0[cur].x, b0); ffma2(acc[0][1], fa0[cur].x, b1);
            ffma2(acc[1][0], fa0[cur].y, b0); ffma2(acc[1][1], fa0[cur].y, b1);
            ffma2(acc[2][0], fa1[cur].x, b0); ffma2(acc[2][1], fa1[cur].x, b1);
            ffma2(acc[3][0], fa1[cur].y, b0); ffma2(acc[3][1], fa1[cur].y, b1);
        }

        if (c < 15) {   // store prefetched chunk into the other buffer
            float* Aw = As + (buf ^ 1) * 16 * ASTR;
            float* Bw = Bs + (buf ^ 1) * 16 * 128;
            Aw[(akp * 2 + 0) * ASTR + arow] = ga.x;
            Aw[(akp * 2 + 1) * ASTR + arow] = ga.y;
            if (RELU_B) {
                gb.x = fmaxf(gb.x, 0.0f); gb.y = fmaxf(gb.y, 0.0f);
                gb.z = fmaxf(gb.z, 0.0f); gb.w = fmaxf(gb.w, 0.0f);
            }
            *(float4*)&Bw[brow * 128 + bcol] = gb;
        }
        __syncthreads();
    }
}

// ---------------------------------------------------------------- W_eff GEMM
// grid (2, 4, 12), 512 threads.
__global__ __launch_bounds__(512) void weff_kernel(const float* __restrict__ adj) {
    __shared__ __align__(16) float As[2 * 16 * ASTR];
    __shared__ __align__(16) float Bs[2 * 16 * 128];
    int nl = blockIdx.z;
    const float* A = g_wsum + (size_t)(nl % 3) * (CC * CC);
    const float* B = adj    + (size_t)(nl / 3) * (CC * CC);
    float* Cc = g_weff + (size_t)nl * (CC * CC);
    int row0 = blockIdx.y * 64, col0 = blockIdx.x * 128;
    int wid = threadIdx.x >> 5, lane = threadIdx.x & 31;
    int wr = wid >> 1, wc = wid & 1;

    u64 acc[4][2] = {};
    gemm_tile<CC, true>(A, B, row0, col0, acc, As, Bs);

    int col = col0 + wc * 64 + lane * 2;
#pragma unroll
    for (int rp = 0; rp < 4; rp++) {
        int r = row0 + wr * 8 + rp * 2;
        float2 p0 = unpk(acc[rp][0]), p1 = unpk(acc[rp][1]);
        *(float2*)(Cc + (r + 0) * CC + col) = make_float2(p0.x, p1.x);
        *(float2*)(Cc + (r + 1) * CC + col) = make_float2(p0.y, p1.y);
    }
}

// ---------------------------------------------------------------- corrections
__global__ __launch_bounds__(256) void corr2_kernel(const float* __restrict__ adj,
                                                    const float* __restrict__ w) {
    int l = blockIdx.x;
    int o = threadIdx.x;
    __shared__ float mcol[CC];
    int ncorr = g_ncorr;
    for (int e = 0; e < ncorr; e++) {
        int ent = g_corr[e];
        int n = ent >> 16, k = (ent >> 10) & 0x3F, b = (ent >> 2) & 0xFF, st = ent & 3;
        __syncthreads();
        mcol[o] = adj[(size_t)n * CC * CC + o * CC + b];
        __syncthreads();
        const float* wrow = w + (size_t)l * CC * SS * CC + (size_t)o * (SS * CC) + k * CC;
        float s = 0.0f;
        if (st == 1) {
            for (int a = 0; a < CC; a++) s = fmaf(wrow[a], fminf(mcol[a], 0.0f), s);
        } else {
            for (int a = 0; a < CC; a++) s = fmaf(-wrow[a], fmaxf(mcol[a], 0.0f), s);
        }
        atomicAdd(&g_weff[(size_t)(n * 3 + l) * CC * CC + o * CC + b], s);
    }
}

// ---------------------------------------------------------------- layer GEMM + BN + ReLU
// grid (8, 4, 4), 512 threads.
__global__ __launch_bounds__(512) void layer_kernel(
    const float* __restrict__ x,
    float* __restrict__ y,
    int l,
    const float* __restrict__ cb,
    const float* __restrict__ gamma,
    const float* __restrict__ beta,
    const float* __restrict__ mean,
    const float* __restrict__ var) {
    __shared__ __align__(16) float As[2 * 16 * ASTR];
    __shared__ __align__(16) float Bs[2 * 16 * 128];
    int n = blockIdx.z;
    const float* A = g_weff + (size_t)(n * 3 + l) * (CC * CC);
    const float* B = x + (size_t)n * (CC * HW);
    float* Cc = y + (size_t)n * (CC * HW);
    int row0 = blockIdx.y * 64, col0 = blockIdx.x * 128;
    int wid = threadIdx.x >> 5, lane = threadIdx.x & 31;
    int wr = wid >> 1, wc = wid & 1;

    u64 acc[4][2] = {};
    gemm_tile<HW, false>(A, B, row0, col0, acc, As, Bs);

    int col = col0 + wc * 64 + lane * 2;
#pragma unroll
    for (int rp = 0; rp < 4; rp++) {
        int r = row0 + wr * 8 + rp * 2;
        float sc0  = gamma[r] * rsqrtf(var[r] + 1e-5f);
        float add0 = (cb[r] - mean[r]) * sc0 + beta[r];
        float sc1  = gamma[r + 1] * rsqrtf(var[r + 1] + 1e-5f);
        float add1 = (cb[r + 1] - mean[r + 1]) * sc1 + beta[r + 1];
        float2 p0 = unpk(acc[rp][0]), p1 = unpk(acc[rp][1]);
        float2 v0 = make_float2(fmaxf(fmaf(p0.x, sc0, add0), 0.0f),
                                fmaxf(fmaf(p1.x, sc0, add0), 0.0f));
        float2 v1 = make_float2(fmaxf(fmaf(p0.y, sc1, add1), 0.0f),
                                fmaxf(fmaf(p1.y, sc1, add1), 0.0f));
        *(float2*)(Cc + (r + 0) * HW + col) = v0;
        *(float2*)(Cc + (r + 1) * HW + col) = v1;
    }
}

// ---------------------------------------------------------------- launch
extern "C" void kernel_launch(void* const* d_in, const int* in_sizes, int n_in,
                              void* d_out, int out_size) {
    (void)in_sizes; (void)n_in; (void)out_size;
    const float* feats = (const float*)d_in[0];  // [4,256,32,32]
    const float* adj   = (const float*)d_in[1];  // [4,256,256]
    const float* convw = (const float*)d_in[2];  // [3,256,4096]
    const float* convb = (const float*)d_in[3];  // [3,256]
    const float* gamma = (const float*)d_in[4];
    const float* beta  = (const float*)d_in[5];
    const float* mean  = (const float*)d_in[6];
    const float* var   = (const float*)d_in[7];
    float* out = (float*)d_out;                  // [3,4,256,32,32]

    reset_kernel<<<1, 1>>>();
    detect_kernel<<<dim3(NB, SS), 256>>>(adj);
    wsum_kernel<<<768, 256>>>(convw);
    weff_kernel<<<dim3(2, 4, NB * 3), 512>>>(adj);
    corr2_kernel<<<3, 256>>>(adj, convw);

    const size_t SEC = (size_t)NB * CC * HW;
    for (int l = 0; l < 3; l++) {
        const float* x = (l == 0) ? feats : (out + (size_t)(l - 1) * SEC);
        layer_kernel<<<dim3(8, 4, NB), 512>>>(
            x, out + (size_t)l * SEC, l,
            convb + l * CC, gamma + l * CC, beta + l * CC,
            mean + l * CC, var + l * CC);
    }
}

// round 10
// speedup vs baseline: 1.4208x; 1.2173x over previous
#include <cuda_runtime.h>
#include <cuda_bf16.h>
#include <cstdint>

// FusionMarkovGNN — algebraically collapsed + mma.sync (HMMA) layers.
//   W_eff[n,l] = conv_w[l] @ mss[n] = wsum_l @ relu(adj_n) + rare exact
//   corrections. Per layer: y = relu(BN(W_eff[n,l] @ x + conv_b)).
// Layers: bf16 3-term split (hi*hi + hi*lo + lo*hi), fp32 accum, via
// portable mma.sync.m16n8k16 (sm_103 base target has no tcgen05).
// Layer computes C^T[p,o] = X^T[p,b] * W^T[b,o]: both operands b-contig,
// plain ldmatrix, no .trans.

#define CC 256
#define SS 16
#define HW 1024
#define NB 4

typedef unsigned long long u64;
typedef uint32_t u32;

__device__ float g_wsum[3 * CC * CC];        // [l][o][a]
__device__ float g_weff[NB * 3 * CC * CC];   // [n][l][o][b]
__device__ u32   g_xpack[2][NB * HW * CC];   // [buf][n][p][b]: (lo16<<16)|hi16
__device__ int   g_ncorr;
__device__ int   g_corr[NB * SS * CC];

// ---------------------------------------------------------------- helpers
__device__ __forceinline__ void ffma2(u64& d, u64 a, u64 b) {
    asm("fma.rn.f32x2 %0, %1, %2, %0;" : "+l"(d) : "l"(a), "l"(b));
}
__device__ __forceinline__ float2 unpk(u64 v) {
    float2 r; asm("mov.b64 {%0, %1}, %2;" : "=f"(r.x), "=f"(r.y) : "l"(v)); return r;
}
__device__ __forceinline__ u32 smem_u32(const void* p) {
    u32 a;
    asm("{ .reg .u64 t; cvta.to.shared.u64 t, %1; cvt.u32.u64 %0, t; }" : "=r"(a) : "l"(p));
    return a;
}
// pack two f32 -> bf16x2 (first arg -> low 16 bits)
__device__ __forceinline__ u32 pk2(float lo, float hi) {
    u32 r; asm("cvt.rn.bf16x2.f32 %0, %1, %2;" : "=r"(r) : "f"(hi), "f"(lo)); return r;
}
__device__ __forceinline__ void splt(float x, float& h, float& l) {
    __nv_bfloat16 bh = __float2bfloat16(x);
    h = __bfloat162float(bh);
    l = x - h;
}
__device__ __forceinline__ u32 packsplit(float y) {
    __nv_bfloat16 bh = __float2bfloat16(y);
    float hf = __bfloat162float(bh);
    __nv_bfloat16 bl = __float2bfloat16(y - hf);
    return ((u32)__bfloat16_as_ushort(bl) << 16) | (u32)__bfloat16_as_ushort(bh);
}
__device__ __forceinline__ void ldm4(u32& r0, u32& r1, u32& r2, u32& r3, u32 addr) {
    asm volatile("ldmatrix.sync.aligned.m8n8.x4.shared.b16 {%0,%1,%2,%3}, [%4];"
                 : "=r"(r0), "=r"(r1), "=r"(r2), "=r"(r3) : "r"(addr));
}
__device__ __forceinline__ void mma16816(float* c, const u32* a, const u32* b) {
    asm volatile(
        "mma.sync.aligned.m16n8k16.row.col.f32.bf16.bf16.f32 "
        "{%0,%1,%2,%3}, {%4,%5,%6,%7}, {%8,%9}, {%0,%1,%2,%3};"
        : "+f"(c[0]), "+f"(c[1]), "+f"(c[2]), "+f"(c[3])
        : "r"(a[0]), "r"(a[1]), "r"(a[2]), "r"(a[3]), "r"(b[0]), "r"(b[1]));
}

// ---------------------------------------------------------------- small kernels
__global__ void reset_kernel() { g_ncorr = 0; }

__global__ void detect_kernel(const float* __restrict__ adj) {
    int n = blockIdx.x, k = blockIdx.y, b = threadIdx.x;
    const float* m = adj + n * CC * CC;
    bool anyp = false, allp = true;
#pragma unroll
    for (int i = 0; i < 16; i++) {
        float v = m[(k * 16 + i) * CC + b];
        anyp = anyp || (v > 0.0f);
        allp = allp && (v > 0.0f);
    }
    if (allp || !anyp) {
        int idx = atomicAdd(&g_ncorr, 1);
        g_corr[idx] = (n << 16) | (k << 10) | (b << 2) | (allp ? 1 : 2);
    }
}

__global__ void wsum_kernel(const float* __restrict__ w) {
    int idx = blockIdx.x * 256 + threadIdx.x;
    int l  = idx >> 16;
    int oa = idx & 0xFFFF;
    int o = oa >> 8, a = oa & 255;
    const float* base = w + (size_t)l * CC * SS * CC + (size_t)o * (SS * CC) + a;
    float s = 0.0f;
#pragma unroll
    for (int k = 0; k < 16; k++) s += base[k * CC];
    g_wsum[idx] = s;
}

// ---------------------------------------------------------------- scalar weff GEMM (R6)
#define ASTR 68
__global__ __launch_bounds__(512) void weff_kernel(const float* __restrict__ adj) {
    __shared__ __align__(16) float As[2 * 16 * ASTR];
    __shared__ __align__(16) float Bs[2 * 16 * 128];
    int nl = blockIdx.z;
    const float* A = g_wsum + (size_t)(nl % 3) * (CC * CC);
    const float* B = adj    + (size_t)(nl / 3) * (CC * CC);
    float* Cc = g_weff + (size_t)nl * (CC * CC);
    int row0 = blockIdx.y * 64, col0 = blockIdx.x * 128;
    int tid = threadIdx.x;
    int wid = tid >> 5, lane = tid & 31;
    int wr = wid >> 1, wc = wid & 1;
    int arow = tid >> 3, akp = tid & 7;
    int brow = tid >> 5, bcol = (tid & 31) * 4;
    const float* Ag = A + (row0 + arow) * CC + akp * 2;
    const float* Bg = B + brow * CC + col0 + bcol;
    int aoff = wr * 8;
    int boff = wc * 64 + lane * 2;

    u64 acc[4][2] = {};
    float2 ga = *(const float2*)(Ag);
    float4 gb = *(const float4*)(Bg);
    {
        As[(akp * 2 + 0) * ASTR + arow] = ga.x;
        As[(akp * 2 + 1) * ASTR + arow] = ga.y;
        gb.x = fmaxf(gb.x, 0.0f); gb.y = fmaxf(gb.y, 0.0f);
        gb.z = fmaxf(gb.z, 0.0f); gb.w = fmaxf(gb.w, 0.0f);
        *(float4*)&Bs[brow * 128 + bcol] = gb;
    }
    __syncthreads();

    for (int c = 0; c < 16; c++) {
        int buf = c & 1;
        const float* Ab = As + buf * 16 * ASTR;
        const float* Bb = Bs + buf * 16 * 128;
        if (c < 15) {
            ga = *(const float2*)(Ag + (c + 1) * 16);
            gb = *(const float4*)(Bg + (size_t)(c + 1) * 16 * CC);
        }
        ulonglong2 fa0[2], fa1[2];
        float2 fb[2];
        fa0[0] = *(const ulonglong2*)&Ab[0 * ASTR + aoff];
        fa1[0] = *(const ulonglong2*)&Ab[0 * ASTR + aoff + 4];
        fb[0]  = *(const float2*)&Bb[0 * 128 + boff];
#pragma unroll
        for (int k = 0; k < 16; k++) {
            int cur = k & 1, nxt = cur ^ 1;
            if (k < 15) {
                fa0[nxt] = *(const ulonglong2*)&Ab[(k + 1) * ASTR + aoff];
                fa1[nxt] = *(const ulonglong2*)&Ab[(k + 1) * ASTR + aoff + 4];
                fb[nxt]  = *(const float2*)&Bb[(k + 1) * 128 + boff];
            }
            u64 b0, b1;
            asm("mov.b64 %0, {%1, %1};" : "=l"(b0) : "f"(fb[cur].x));
            asm("mov.b64 %0, {%1, %1};" : "=l"(b1) : "f"(fb[cur].y));
            ffma2(acc[0][0], fa0[cur].x, b0); ffma2(acc[0][1], fa0[cur].x, b1);
            ffma2(acc[1][0], fa0[cur].y, b0); ffma2(acc[1][1], fa0[cur].y, b1);
            ffma2(acc[2][0], fa1[cur].x, b0); ffma2(acc[2][1], fa1[cur].x, b1);
            ffma2(acc[3][0], fa1[cur].y, b0); ffma2(acc[3][1], fa1[cur].y, b1);
        }
        if (c < 15) {
            float* Aw = As + (buf ^ 1) * 16 * ASTR;
            float* Bw = Bs + (buf ^ 1) * 16 * 128;
            Aw[(akp * 2 + 0) * ASTR + arow] = ga.x;
            Aw[(akp * 2 + 1) * ASTR + arow] = ga.y;
            gb.x = fmaxf(gb.x, 0.0f); gb.y = fmaxf(gb.y, 0.0f);
            gb.z = fmaxf(gb.z, 0.0f); gb.w = fmaxf(gb.w, 0.0f);
            *(float4*)&Bw[brow * 128 + bcol] = gb;
        }
        __syncthreads();
    }

    int col = col0 + wc * 64 + lane * 2;
#pragma unroll
    for (int rp = 0; rp < 4; rp++) {
        int r = row0 + wr * 8 + rp * 2;
        float2 p0 = unpk(acc[rp][0]), p1 = unpk(acc[rp][1]);
        *(float2*)(Cc + (r + 0) * CC + col) = make_float2(p0.x, p1.x);
        *(float2*)(Cc + (r + 1) * CC + col) = make_float2(p0.y, p1.y);
    }
}

// ---------------------------------------------------------------- corrections
__global__ __launch_bounds__(256) void corr2_kernel(const float* __restrict__ adj,
                                                    const float* __restrict__ w) {
    int l = blockIdx.x;
    int o = threadIdx.x;
    __shared__ float mcol[CC];
    int ncorr = g_ncorr;
    for (int e = 0; e < ncorr; e++) {
        int ent = g_corr[e];
        int n = ent >> 16, k = (ent >> 10) & 0x3F, b = (ent >> 2) & 0xFF, st = ent & 3;
        __syncthreads();
        mcol[o] = adj[(size_t)n * CC * CC + o * CC + b];
        __syncthreads();
        const float* wrow = w + (size_t)l * CC * SS * CC + (size_t)o * (SS * CC) + k * CC;
        float s = 0.0f;
        if (st == 1) {
            for (int a = 0; a < CC; a++) s = fmaf(wrow[a], fminf(mcol[a], 0.0f), s);
        } else {
            for (int a = 0; a < CC; a++) s = fmaf(-wrow[a], fmaxf(mcol[a], 0.0f), s);
        }
        atomicAdd(&g_weff[(size_t)(n * 3 + l) * CC * CC + o * CC + b], s);
    }
}

// ---------------------------------------------------------------- prep: feats -> xpack[0]
// feats [n][b][p] fp32 -> g_xpack[0][n][p][b] packed bf16 hi/lo
__global__ void prep_kernel(const float* __restrict__ feats) {
    __shared__ float t[32][33];
    int n = blockIdx.z, p0 = blockIdx.x * 32, b0 = blockIdx.y * 32;
    int tx = threadIdx.x & 31, ty = threadIdx.x >> 5;
    const float* f = feats + ((size_t)n * CC + b0) * HW + p0;
#pragma unroll
    for (int i = 0; i < 4; i++) {
        int b = ty + i * 8;
        t[b][tx] = f[(size_t)b * HW + tx];
    }
    __syncthreads();
    u32* xp = g_xpack[0] + ((size_t)n * HW + p0) * CC + b0;
#pragma unroll
    for (int i = 0; i < 4; i++) {
        int p = ty + i * 8;
        xp[(size_t)p * CC + tx] = packsplit(t[tx][p]);
    }
}

// ---------------------------------------------------------------- mma.sync layer
// Block tile: 128 (p) x 64 (o), K = 256 in 8 chunks of 32. 256 threads,
// 8 warps as 4(m=p) x 2(n=o), warp tile 32x32.
// smem: staging XHI/XLO [128][40 b16], WHI/WLO [64][40 b16]; epilogue Ds[128][66] f32.
#define S_XHI 0
#define S_XLO 10240
#define S_WHI 20480
#define S_WLO 25600
#define S_DS  0
#define S_CSC 33792
#define S_CAD (33792 + 256)
#define S_TOT (33792 + 512)

// IN_BUF / OUT_BUF select g_xpack ping-pong (OUT_BUF < 0: no pack output).
template <int IN_BUF, int OUT_BUF>
__global__ __launch_bounds__(256) void layer_mma(
    float* __restrict__ Y,         // fp32 out section [n][o][p]
    int l,
    const float* __restrict__ cb_, const float* __restrict__ gamma_,
    const float* __restrict__ beta_, const float* __restrict__ mean_,
    const float* __restrict__ var_) {
    __shared__ __align__(16) unsigned char sraw[S_TOT];
    u32 sb = smem_u32(sraw);
    int tid = threadIdx.x;
    int wid = tid >> 5, lane = tid & 31;
    int wm = wid >> 1, wn = wid & 1;          // warp grid 4(m) x 2(n)
    int m0 = wm * 32, n0 = wn * 32;

    int n = blockIdx.z;
    int pcol0 = blockIdx.x * 128;             // p tile
    int o0 = blockIdx.y * 64;                 // o tile
    const u32* Xp = g_xpack[IN_BUF] + ((size_t)n * HW + pcol0) * CC;
    const float* Wp = g_weff + (size_t)(n * 3 + l) * CC * CC + (size_t)o0 * CC;

    // ldmatrix lane addressing
    int la = lane & 15, lb = (lane >> 4) & 1;             // A: row la, k-half lb
    int brr = (lane & 7) + ((lane & 16) ? 8 : 0);         // B: row within n16
    int bhalf = (lane >> 3) & 1;                          // B: k-half

    float acc[2][4][4] = {};

    // staging indices
    int xp_p[4], xp_u[4];
#pragma unroll
    for (int i = 0; i < 4; i++) { int idx = tid + 256 * i; xp_p[i] = idx >> 3; xp_u[i] = idx & 7; }
    int wo[2], wu[2];
#pragma unroll
    for (int i = 0; i < 2; i++) { int idx = tid + 256 * i; wo[i] = idx >> 3; wu[i] = idx & 7; }

    uint4 gx[4];
    float4 gw[2];
#pragma unroll
    for (int i = 0; i < 4; i++)
        gx[i] = *(const uint4*)(Xp + (size_t)xp_p[i] * CC + xp_u[i] * 4);
#pragma unroll
    for (int i = 0; i < 2; i++)
        gw[i] = *(const float4*)(Wp + (size_t)wo[i] * CC + wu[i] * 4);

    for (int kc = 0; kc < 8; kc++) {
        // store staged chunk into smem
#pragma unroll
        for (int i = 0; i < 4; i++) {
            u32 v0 = gx[i].x, v1 = gx[i].y, v2 = gx[i].z, v3 = gx[i].w;
            uint2 h = make_uint2((v0 & 0xFFFFu) | (v1 << 16), (v2 & 0xFFFFu) | (v3 << 16));
            uint2 lo = make_uint2((v0 >> 16) | (v1 & 0xFFFF0000u), (v2 >> 16) | (v3 & 0xFFFF0000u));
            *(uint2*)(sraw + S_XHI + xp_p[i] * 80 + xp_u[i] * 8) = h;
            *(uint2*)(sraw + S_XLO + xp_p[i] * 80 + xp_u[i] * 8) = lo;
        }
#pragma unroll
        for (int i = 0; i < 2; i++) {
            float h0, h1, h2, h3, l0, l1, l2, l3;
            splt(gw[i].x, h0, l0); splt(gw[i].y, h1, l1);
            splt(gw[i].z, h2, l2); splt(gw[i].w, h3, l3);
            *(uint2*)(sraw + S_WHI + wo[i] * 80 + wu[i] * 8) = make_uint2(pk2(h0, h1), pk2(h2, h3));
            *(uint2*)(sraw + S_WLO + wo[i] * 80 + wu[i] * 8) = make_uint2(pk2(l0, l1), pk2(l2, l3));
        }
        __syncthreads();

        if (kc < 7) {   // prefetch next chunk
            int b0 = (kc + 1) * 32;
#pragma unroll
            for (int i = 0; i < 4; i++)
                gx[i] = *(const uint4*)(Xp + (size_t)xp_p[i] * CC + b0 + xp_u[i] * 4);
#pragma unroll
            for (int i = 0; i < 2; i++)
                gw[i] = *(const float4*)(Wp + (size_t)wo[i] * CC + b0 + wu[i] * 4);
        }

#pragma unroll
        for (int ks = 0; ks < 2; ks++) {
            u32 ahi[2][4], alo[2][4];
#pragma unroll
            for (int mi = 0; mi < 2; mi++) {
                u32 off = (u32)((m0 + mi * 16 + la) * 80 + ks * 32 + lb * 16);
                ldm4(ahi[mi][0], ahi[mi][1], ahi[mi][2], ahi[mi][3], sb + S_XHI + off);
                ldm4(alo[mi][0], alo[mi][1], alo[mi][2], alo[mi][3], sb + S_XLO + off);
            }
            u32 bh[4][2], bl[4][2];
#pragma unroll
            for (int g = 0; g < 2; g++) {
                u32 off = (u32)((n0 + g * 16 + brr) * 80 + ks * 32 + bhalf * 16);
                u32 r0, r1, r2, r3;
                ldm4(r0, r1, r2, r3, sb + S_WHI + off);
                bh[g * 2][0] = r0; bh[g * 2][1] = r1;
                bh[g * 2 + 1][0] = r2; bh[g * 2 + 1][1] = r3;
                ldm4(r0, r1, r2, r3, sb + S_WLO + off);
                bl[g * 2][0] = r0; bl[g * 2][1] = r1;
                bl[g * 2 + 1][0] = r2; bl[g * 2 + 1][1] = r3;
            }
#pragma unroll
            for (int mi = 0; mi < 2; mi++)
#pragma unroll
                for (int ni = 0; ni < 4; ni++) {
                    mma16816(acc[mi][ni], ahi[mi], bh[ni]);
                    mma16816(acc[mi][ni], ahi[mi], bl[ni]);
                    mma16816(acc[mi][ni], alo[mi], bh[ni]);
                }
        }
        __syncthreads();
    }

    // ---- epilogue
    float* Ds  = (float*)(sraw + S_DS);
    float* csc = (float*)(sraw + S_CSC);
    float* cad = (float*)(sraw + S_CAD);
    if (tid < 64) {
        int o = o0 + tid;
        float sc = gamma_[o] * rsqrtf(var_[o] + 1e-5f);
        csc[tid] = sc;
        cad[tid] = (cb_[o] - mean_[o]) * sc + beta_[o];
    }
    int pr = lane >> 2, oc = (lane & 3) * 2;
#pragma unroll
    for (int mi = 0; mi < 2; mi++)
#pragma unroll
        for (int ni = 0; ni < 4; ni++) {
            int p = m0 + mi * 16 + pr;
            int o = n0 + ni * 8 + oc;
            *(float2*)&Ds[p * 66 + o]       = make_float2(acc[mi][ni][0], acc[mi][ni][1]);
            *(float2*)&Ds[(p + 8) * 66 + o] = make_float2(acc[mi][ni][2], acc[mi][ni][3]);
        }
    __syncthreads();

    float* Yn = Y + (size_t)n * CC * HW;
    for (int idx = tid; idx < 64 * 128; idx += 256) {
        int o = idx >> 7, p = idx & 127;
        float v = fmaxf(fmaf(Ds[p * 66 + o], csc[o], cad[o]), 0.0f);
        Yn[(size_t)(o0 + o) * HW + pcol0 + p] = v;
    }
    if (OUT_BUF >= 0) {
        u32* Xo = g_xpack[OUT_BUF < 0 ? 0 : OUT_BUF] + ((size_t)n * HW + pcol0) * CC + o0;
        for (int idx = tid; idx < 128 * 64; idx += 256) {
            int p = idx >> 6, o = idx & 63;
            float v = fmaxf(fmaf(Ds[p * 66 + o], csc[o], cad[o]), 0.0f);
            Xo[(size_t)p * CC + o] = packsplit(v);
        }
    }
}

// ---------------------------------------------------------------- launch
extern "C" void kernel_launch(void* const* d_in, const int* in_sizes, int n_in,
                              void* d_out, int out_size) {
    (void)in_sizes; (void)n_in; (void)out_size;
    const float* feats = (const float*)d_in[0];  // [4,256,32,32]
    const float* adj   = (const float*)d_in[1];  // [4,256,256]
    const float* convw = (const float*)d_in[2];  // [3,256,4096]
    const float* convb = (const float*)d_in[3];  // [3,256]
    const float* gamma = (const float*)d_in[4];
    const float* beta  = (const float*)d_in[5];
    const float* mean  = (const float*)d_in[6];
    const float* var   = (const float*)d_in[7];
    float* out = (float*)d_out;                  // [3,4,256,32,32]

    reset_kernel<<<1, 1>>>();
    detect_kernel<<<dim3(NB, SS), 256>>>(adj);
    wsum_kernel<<<768, 256>>>(convw);
    weff_kernel<<<dim3(2, 4, NB * 3), 512>>>(adj);
    corr2_kernel<<<3, 256>>>(adj, convw);
    prep_kernel<<<dim3(32, 8, NB), 256>>>(feats);

    const size_t SEC = (size_t)NB * CC * HW;
    dim3 grid(HW / 128, CC / 64, NB);
    layer_mma<0, 1><<<grid, 256>>>(
        out, 0,
        convb + 0 * CC, gamma + 0 * CC, beta + 0 * CC, mean + 0 * CC, var + 0 * CC);
    layer_mma<1, 0><<<grid, 256>>>(
        out + SEC, 1,
        convb + 1 * CC, gamma + 1 * CC, beta + 1 * CC, mean + 1 * CC, var + 1 * CC);
    layer_mma<0, -1><<<grid, 256>>>(
        out + 2 * SEC, 2,
        convb + 2 * CC, gamma + 2 * CC, beta + 2 * CC, mean + 2 * CC, var + 2 * CC);
}

// round 14
// speedup vs baseline: 1.5259x; 1.0740x over previous
#include <cuda_runtime.h>
#include <cuda_bf16.h>
#include <cstdint>

// FusionMarkovGNN — algebraically collapsed, all GEMMs on mma.sync (HMMA).
//   W_eff[n,l] = conv_w[l] @ mss[n] = wsum_l @ relu(adj_n) + rare exact
//   corrections. Per layer: y = relu(BN(W_eff[n,l] @ x + conv_b)).
// bf16 3-term split (hi*hi + hi*lo + lo*hi), fp32 accum, m16n8k16.
// NOTE: device globals are referenced ONLY in device code (host-side
// references to __device__ symbols are UB — caused the R12 failure).

#define CC 256
#define SS 16
#define HW 1024
#define NB 4

typedef unsigned long long u64;
typedef uint32_t u32;

__device__ u32   g_wspack[3 * CC * CC];      // [l][o][a] packed split of wsum
__device__ u32   g_apack[NB * CC * CC];      // [n][b][a] packed split of relu(adj^T)
__device__ float g_weff[NB * 3 * CC * CC];   // [n][l][o][b]
__device__ u32   g_xpack[2][NB * HW * CC];   // [buf][n][p][b]: (lo16<<16)|hi16
__device__ int   g_ncorr;
__device__ int   g_corr[NB * SS * CC];

// ---------------------------------------------------------------- helpers
__device__ __forceinline__ u32 smem_u32(const void* p) {
    u32 a;
    asm("{ .reg .u64 t; cvta.to.shared.u64 t, %1; cvt.u32.u64 %0, t; }" : "=r"(a) : "l"(p));
    return a;
}
__device__ __forceinline__ u32 pk2(float lo, float hi) {
    u32 r; asm("cvt.rn.bf16x2.f32 %0, %1, %2;" : "=r"(r) : "f"(hi), "f"(lo)); return r;
}
__device__ __forceinline__ void splt(float x, float& h, float& l) {
    __nv_bfloat16 bh = __float2bfloat16(x);
    h = __bfloat162float(bh);
    l = x - h;
}
__device__ __forceinline__ u32 packsplit(float y) {
    __nv_bfloat16 bh = __float2bfloat16(y);
    float hf = __bfloat162float(bh);
    __nv_bfloat16 bl = __float2bfloat16(y - hf);
    return ((u32)__bfloat16_as_ushort(bl) << 16) | (u32)__bfloat16_as_ushort(bh);
}
__device__ __forceinline__ void ldm4(u32& r0, u32& r1, u32& r2, u32& r3, u32 addr) {
    asm volatile("ldmatrix.sync.aligned.m8n8.x4.shared.b16 {%0,%1,%2,%3}, [%4];"
                 : "=r"(r0), "=r"(r1), "=r"(r2), "=r"(r3) : "r"(addr));
}
__device__ __forceinline__ void mma16816(float* c, const u32* a, const u32* b) {
    asm volatile(
        "mma.sync.aligned.m16n8k16.row.col.f32.bf16.bf16.f32 "
        "{%0,%1,%2,%3}, {%4,%5,%6,%7}, {%8,%9}, {%0,%1,%2,%3};"
        : "+f"(c[0]), "+f"(c[1]), "+f"(c[2]), "+f"(c[3])
        : "r"(a[0]), "r"(a[1]), "r"(a[2]), "r"(a[3]), "r"(b[0]), "r"(b[1]));
}

// ---------------------------------------------------------------- small kernels
__global__ void detect_kernel(const float* __restrict__ adj) {
    int n = blockIdx.x, k = blockIdx.y, b = threadIdx.x;
    const float* m = adj + n * CC * CC;
    bool anyp = false, allp = true;
#pragma unroll
    for (int i = 0; i < 16; i++) {
        float v = m[(k * 16 + i) * CC + b];
        anyp = anyp || (v > 0.0f);
        allp = allp && (v > 0.0f);
    }
    if (allp || !anyp) {
        int idx = atomicAdd(&g_ncorr, 1);
        g_corr[idx] = (n << 16) | (k << 10) | (b << 2) | (allp ? 1 : 2);
    }
}

// wsum (packed split) + g_ncorr reset (runs before detect in stream order)
__global__ void wsum_kernel(const float* __restrict__ w) {
    if (blockIdx.x == 0 && threadIdx.x == 0) g_ncorr = 0;
    int idx = blockIdx.x * 256 + threadIdx.x;
    int l  = idx >> 16;
    int oa = idx & 0xFFFF;
    int o = oa >> 8, a = oa & 255;
    const float* base = w + (size_t)l * CC * SS * CC + (size_t)o * (SS * CC) + a;
    float s = 0.0f;
#pragma unroll
    for (int k = 0; k < 16; k++) s += base[k * CC];
    g_wspack[idx] = packsplit(s);
}

// adjprep: g_apack[n][b][a] = packsplit(relu(adj[n][a][b]))
__global__ void adjprep_kernel(const float* __restrict__ adj) {
    __shared__ float t[32][33];
    int n = blockIdx.z, a0 = blockIdx.x * 32, b0 = blockIdx.y * 32;
    int tx = threadIdx.x & 31, ty = threadIdx.x >> 5;
    const float* m = adj + (size_t)n * CC * CC;
#pragma unroll
    for (int i = 0; i < 4; i++) {
        int a = ty + i * 8;
        t[a][tx] = m[(size_t)(a0 + a) * CC + b0 + tx];
    }
    __syncthreads();
    u32* ap = g_apack + (size_t)n * CC * CC;
#pragma unroll
    for (int i = 0; i < 4; i++) {
        int b = ty + i * 8;
        ap[(size_t)(b0 + b) * CC + a0 + tx] = packsplit(fmaxf(t[tx][b], 0.0f));
    }
}

// prep: feats [n][b][p] fp32 -> g_xpack[0][n][p][b] packed bf16 hi/lo
__global__ void prep_kernel(const float* __restrict__ feats) {
    __shared__ float t[32][33];
    int n = blockIdx.z, p0 = blockIdx.x * 32, b0 = blockIdx.y * 32;
    int tx = threadIdx.x & 31, ty = threadIdx.x >> 5;
    const float* f = feats + ((size_t)n * CC + b0) * HW + p0;
#pragma unroll
    for (int i = 0; i < 4; i++) {
        int b = ty + i * 8;
        t[b][tx] = f[(size_t)b * HW + tx];
    }
    __syncthreads();
    u32* xp = g_xpack[0] + ((size_t)n * HW + p0) * CC + b0;
#pragma unroll
    for (int i = 0; i < 4; i++) {
        int p = ty + i * 8;
        xp[(size_t)p * CC + tx] = packsplit(t[tx][p]);
    }
}

// ---------------------------------------------------------------- corrections
__global__ __launch_bounds__(256) void corr2_kernel(const float* __restrict__ adj,
                                                    const float* __restrict__ w) {
    int l = blockIdx.x;
    int o = threadIdx.x;
    __shared__ float mcol[CC];
    int ncorr = g_ncorr;
    for (int e = 0; e < ncorr; e++) {
        int ent = g_corr[e];
        int n = ent >> 16, k = (ent >> 10) & 0x3F, b = (ent >> 2) & 0xFF, st = ent & 3;
        __syncthreads();
        mcol[o] = adj[(size_t)n * CC * CC + o * CC + b];
        __syncthreads();
        const float* wrow = w + (size_t)l * CC * SS * CC + (size_t)o * (SS * CC) + k * CC;
        float s = 0.0f;
        if (st == 1) {
            for (int a = 0; a < CC; a++) s = fmaf(wrow[a], fminf(mcol[a], 0.0f), s);
        } else {
            for (int a = 0; a < CC; a++) s = fmaf(-wrow[a], fmaxf(mcol[a], 0.0f), s);
        }
        atomicAdd(&g_weff[(size_t)(n * 3 + l) * CC * CC + o * CC + b], s);
    }
}

// ---------------------------------------------------------------- shared smem layout
#define S_XHI 0
#define S_XLO 10240
#define S_WHI 20480
#define S_WLO 25600
#define S_DS  0
#define S_CSC 33792
#define S_CAD (33792 + 256)
#define S_TOT (33792 + 512)

// ---------------------------------------------------------------- weff via mma
// C[o][b] = wsum_l[o][a] @ relu(adj_n)^T[b][a]. Tile 128(o) x 64(b), K=256.
// Both operands pre-packed; staging is unzip only. Grid (2, 4, 12).
__global__ __launch_bounds__(256) void weff_mma() {
    __shared__ __align__(16) unsigned char sraw[S_TOT];
    u32 sb = smem_u32(sraw);
    int tid = threadIdx.x;
    int wid = tid >> 5, lane = tid & 31;
    int wm = wid >> 1, wn = wid & 1;
    int m0 = wm * 32, n0 = wn * 32;

    int nl = blockIdx.z;
    int o0 = blockIdx.x * 128;
    int b0 = blockIdx.y * 64;
    const u32* Ap = g_wspack + (size_t)(nl % 3) * CC * CC + (size_t)o0 * CC;
    const u32* Bp = g_apack  + (size_t)(nl / 3) * CC * CC + (size_t)b0 * CC;
    float* Cc = g_weff + (size_t)nl * CC * CC;

    int la = lane & 15, lb = (lane >> 4) & 1;
    int brr = (lane & 7) + ((lane & 16) ? 8 : 0);
    int bhalf = (lane >> 3) & 1;

    float acc[2][4][4] = {};

    int xp_p[4], xp_u[4];
#pragma unroll
    for (int i = 0; i < 4; i++) { int idx = tid + 256 * i; xp_p[i] = idx >> 3; xp_u[i] = idx & 7; }
    int wo[2], wu[2];
#pragma unroll
    for (int i = 0; i < 2; i++) { int idx = tid + 256 * i; wo[i] = idx >> 3; wu[i] = idx & 7; }

    uint4 gx[4], gw[2];
#pragma unroll
    for (int i = 0; i < 4; i++)
        gx[i] = *(const uint4*)(Ap + (size_t)xp_p[i] * CC + xp_u[i] * 4);
#pragma unroll
    for (int i = 0; i < 2; i++)
        gw[i] = *(const uint4*)(Bp + (size_t)wo[i] * CC + wu[i] * 4);

    for (int kc = 0; kc < 8; kc++) {
#pragma unroll
        for (int i = 0; i < 4; i++) {
            u32 v0 = gx[i].x, v1 = gx[i].y, v2 = gx[i].z, v3 = gx[i].w;
            *(uint2*)(sraw + S_XHI + xp_p[i] * 80 + xp_u[i] * 8) =
                make_uint2((v0 & 0xFFFFu) | (v1 << 16), (v2 & 0xFFFFu) | (v3 << 16));
            *(uint2*)(sraw + S_XLO + xp_p[i] * 80 + xp_u[i] * 8) =
                make_uint2((v0 >> 16) | (v1 & 0xFFFF0000u), (v2 >> 16) | (v3 & 0xFFFF0000u));
        }
#pragma unroll
        for (int i = 0; i < 2; i++) {
            u32 v0 = gw[i].x, v1 = gw[i].y, v2 = gw[i].z, v3 = gw[i].w;
            *(uint2*)(sraw + S_WHI + wo[i] * 80 + wu[i] * 8) =
                make_uint2((v0 & 0xFFFFu) | (v1 << 16), (v2 & 0xFFFFu) | (v3 << 16));
            *(uint2*)(sraw + S_WLO + wo[i] * 80 + wu[i] * 8) =
                make_uint2((v0 >> 16) | (v1 & 0xFFFF0000u), (v2 >> 16) | (v3 & 0xFFFF0000u));
        }
        __syncthreads();

        if (kc < 7) {
            int a0 = (kc + 1) * 32;
#pragma unroll
            for (int i = 0; i < 4; i++)
                gx[i] = *(const uint4*)(Ap + (size_t)xp_p[i] * CC + a0 + xp_u[i] * 4);
#pragma unroll
            for (int i = 0; i < 2; i++)
                gw[i] = *(const uint4*)(Bp + (size_t)wo[i] * CC + a0 + wu[i] * 4);
        }

#pragma unroll
        for (int ks = 0; ks < 2; ks++) {
            u32 ahi[2][4], alo[2][4];
#pragma unroll
            for (int mi = 0; mi < 2; mi++) {
                u32 off = (u32)((m0 + mi * 16 + la) * 80 + ks * 32 + lb * 16);
                ldm4(ahi[mi][0], ahi[mi][1], ahi[mi][2], ahi[mi][3], sb + S_XHI + off);
                ldm4(alo[mi][0], alo[mi][1], alo[mi][2], alo[mi][3], sb + S_XLO + off);
            }
            u32 bh[4][2], bl[4][2];
#pragma unroll
            for (int g = 0; g < 2; g++) {
                u32 off = (u32)((n0 + g * 16 + brr) * 80 + ks * 32 + bhalf * 16);
                u32 r0, r1, r2, r3;
                ldm4(r0, r1, r2, r3, sb + S_WHI + off);
                bh[g * 2][0] = r0; bh[g * 2][1] = r1;
                bh[g * 2 + 1][0] = r2; bh[g * 2 + 1][1] = r3;
                ldm4(r0, r1, r2, r3, sb + S_WLO + off);
                bl[g * 2][0] = r0; bl[g * 2][1] = r1;
                bl[g * 2 + 1][0] = r2; bl[g * 2 + 1][1] = r3;
            }
#pragma unroll
            for (int mi = 0; mi < 2; mi++)
#pragma unroll
                for (int ni = 0; ni < 4; ni++) {
                    mma16816(acc[mi][ni], ahi[mi], bh[ni]);
                    mma16816(acc[mi][ni], ahi[mi], bl[ni]);
                    mma16816(acc[mi][ni], alo[mi], bh[ni]);
                }
        }
        __syncthreads();
    }

    int pr = lane >> 2, oc = (lane & 3) * 2;
#pragma unroll
    for (int mi = 0; mi < 2; mi++)
#pragma unroll
        for (int ni = 0; ni < 4; ni++) {
            int o = o0 + m0 + mi * 16 + pr;
            int b = b0 + n0 + ni * 8 + oc;
            *(float2*)(Cc + (size_t)o * CC + b) =
                make_float2(acc[mi][ni][0], acc[mi][ni][1]);
            *(float2*)(Cc + (size_t)(o + 8) * CC + b) =
                make_float2(acc[mi][ni][2], acc[mi][ni][3]);
        }
}

// ---------------------------------------------------------------- mma.sync layer
// Block tile: 128 (p) x 64 (o), K = 256 in 8 chunks of 32. 256 threads.
template <int IN_BUF, int OUT_BUF>
__global__ __launch_bounds__(256) void layer_mma(
    float* __restrict__ Y,
    int l,
    const float* __restrict__ cb_, const float* __restrict__ gamma_,
    const float* __restrict__ beta_, const float* __restrict__ mean_,
    const float* __restrict__ var_) {
    __shared__ __align__(16) unsigned char sraw[S_TOT];
    u32 sb = smem_u32(sraw);
    int tid = threadIdx.x;
    int wid = tid >> 5, lane = tid & 31;
    int wm = wid >> 1, wn = wid & 1;
    int m0 = wm * 32, n0 = wn * 32;

    int n = blockIdx.z;
    int pcol0 = blockIdx.x * 128;
    int o0 = blockIdx.y * 64;
    const u32* Xp = g_xpack[IN_BUF] + ((size_t)n * HW + pcol0) * CC;
    const float* Wp = g_weff + (size_t)(n * 3 + l) * CC * CC + (size_t)o0 * CC;

    int la = lane & 15, lb = (lane >> 4) & 1;
    int brr = (lane & 7) + ((lane & 16) ? 8 : 0);
    int bhalf = (lane >> 3) & 1;

    float acc[2][4][4] = {};

    int xp_p[4], xp_u[4];
#pragma unroll
    for (int i = 0; i < 4; i++) { int idx = tid + 256 * i; xp_p[i] = idx >> 3; xp_u[i] = idx & 7; }
    int wo[2], wu[2];
#pragma unroll
    for (int i = 0; i < 2; i++) { int idx = tid + 256 * i; wo[i] = idx >> 3; wu[i] = idx & 7; }

    uint4 gx[4];
    float4 gw[2];
#pragma unroll
    for (int i = 0; i < 4; i++)
        gx[i] = *(const uint4*)(Xp + (size_t)xp_p[i] * CC + xp_u[i] * 4);
#pragma unroll
    for (int i = 0; i < 2; i++)
        gw[i] = *(const float4*)(Wp + (size_t)wo[i] * CC + wu[i] * 4);

    for (int kc = 0; kc < 8; kc++) {
#pragma unroll
        for (int i = 0; i < 4; i++) {
            u32 v0 = gx[i].x, v1 = gx[i].y, v2 = gx[i].z, v3 = gx[i].w;
            *(uint2*)(sraw + S_XHI + xp_p[i] * 80 + xp_u[i] * 8) =
                make_uint2((v0 & 0xFFFFu) | (v1 << 16), (v2 & 0xFFFFu) | (v3 << 16));
            *(uint2*)(sraw + S_XLO + xp_p[i] * 80 + xp_u[i] * 8) =
                make_uint2((v0 >> 16) | (v1 & 0xFFFF0000u), (v2 >> 16) | (v3 & 0xFFFF0000u));
        }
#pragma unroll
        for (int i = 0; i < 2; i++) {
            float h0, h1, h2, h3, l0, l1, l2, l3;
            splt(gw[i].x, h0, l0); splt(gw[i].y, h1, l1);
            splt(gw[i].z, h2, l2); splt(gw[i].w, h3, l3);
            *(uint2*)(sraw + S_WHI + wo[i] * 80 + wu[i] * 8) = make_uint2(pk2(h0, h1), pk2(h2, h3));
            *(uint2*)(sraw + S_WLO + wo[i] * 80 + wu[i] * 8) = make_uint2(pk2(l0, l1), pk2(l2, l3));
        }
        __syncthreads();

        if (kc < 7) {
            int b0 = (kc + 1) * 32;
#pragma unroll
            for (int i = 0; i < 4; i++)
                gx[i] = *(const uint4*)(Xp + (size_t)xp_p[i] * CC + b0 + xp_u[i] * 4);
#pragma unroll
            for (int i = 0; i < 2; i++)
                gw[i] = *(const float4*)(Wp + (size_t)wo[i] * CC + b0 + wu[i] * 4);
        }

#pragma unroll
        for (int ks = 0; ks < 2; ks++) {
            u32 ahi[2][4], alo[2][4];
#pragma unroll
            for (int mi = 0; mi < 2; mi++) {
                u32 off = (u32)((m0 + mi * 16 + la) * 80 + ks * 32 + lb * 16);
                ldm4(ahi[mi][0], ahi[mi][1], ahi[mi][2], ahi[mi][3], sb + S_XHI + off);
                ldm4(alo[mi][0], alo[mi][1], alo[mi][2], alo[mi][3], sb + S_XLO + off);
            }
            u32 bh[4][2], bl[4][2];
#pragma unroll
            for (int g = 0; g < 2; g++) {
                u32 off = (u32)((n0 + g * 16 + brr) * 80 + ks * 32 + bhalf * 16);
                u32 r0, r1, r2, r3;
                ldm4(r0, r1, r2, r3, sb + S_WHI + off);
                bh[g * 2][0] = r0; bh[g * 2][1] = r1;
                bh[g * 2 + 1][0] = r2; bh[g * 2 + 1][1] = r3;
                ldm4(r0, r1, r2, r3, sb + S_WLO + off);
                bl[g * 2][0] = r0; bl[g * 2][1] = r1;
                bl[g * 2 + 1][0] = r2; bl[g * 2 + 1][1] = r3;
            }
#pragma unroll
            for (int mi = 0; mi < 2; mi++)
#pragma unroll
                for (int ni = 0; ni < 4; ni++) {
                    mma16816(acc[mi][ni], ahi[mi], bh[ni]);
                    mma16816(acc[mi][ni], ahi[mi], bl[ni]);
                    mma16816(acc[mi][ni], alo[mi], bh[ni]);
                }
        }
        __syncthreads();
    }

    // ---- epilogue
    float* Ds  = (float*)(sraw + S_DS);
    float* csc = (float*)(sraw + S_CSC);
    float* cad = (float*)(sraw + S_CAD);
    if (tid < 64) {
        int o = o0 + tid;
        float sc = gamma_[o] * rsqrtf(var_[o] + 1e-5f);
        csc[tid] = sc;
        cad[tid] = (cb_[o] - mean_[o]) * sc + beta_[o];
    }
    int pr = lane >> 2, oc = (lane & 3) * 2;
#pragma unroll
    for (int mi = 0; mi < 2; mi++)
#pragma unroll
        for (int ni = 0; ni < 4; ni++) {
            int p = m0 + mi * 16 + pr;
            int o = n0 + ni * 8 + oc;
            *(float2*)&Ds[p * 66 + o]       = make_float2(acc[mi][ni][0], acc[mi][ni][1]);
            *(float2*)&Ds[(p + 8) * 66 + o] = make_float2(acc[mi][ni][2], acc[mi][ni][3]);
        }
    __syncthreads();

    float* Yn = Y + (size_t)n * CC * HW;
    for (int idx = tid; idx < 64 * 128; idx += 256) {
        int o = idx >> 7, p = idx & 127;
        float v = fmaxf(fmaf(Ds[p * 66 + o], csc[o], cad[o]), 0.0f);
        Yn[(size_t)(o0 + o) * HW + pcol0 + p] = v;
    }
    if (OUT_BUF >= 0) {
        u32* Xo = g_xpack[OUT_BUF < 0 ? 0 : OUT_BUF] + ((size_t)n * HW + pcol0) * CC + o0;
        for (int idx = tid; idx < 128 * 64; idx += 256) {
            int p = idx >> 6, o = idx & 63;
            float v = fmaxf(fmaf(Ds[p * 66 + o], csc[o], cad[o]), 0.0f);
            Xo[(size_t)p * CC + o] = packsplit(v);
        }
    }
}

// ---------------------------------------------------------------- launch
extern "C" void kernel_launch(void* const* d_in, const int* in_sizes, int n_in,
                              void* d_out, int out_size) {
    (void)in_sizes; (void)n_in; (void)out_size;
    const float* feats = (const float*)d_in[0];  // [4,256,32,32]
    const float* adj   = (const float*)d_in[1];  // [4,256,256]
    const float* convw = (const float*)d_in[2];  // [3,256,4096]
    const float* convb = (const float*)d_in[3];  // [3,256]
    const float* gamma = (const float*)d_in[4];
    const float* beta  = (const float*)d_in[5];
    const float* mean  = (const float*)d_in[6];
    const float* var   = (const float*)d_in[7];
    float* out = (float*)d_out;                  // [3,4,256,32,32]

    wsum_kernel<<<768, 256>>>(convw);            // also resets g_ncorr
    detect_kernel<<<dim3(NB, SS), 256>>>(adj);
    adjprep_kernel<<<dim3(8, 8, NB), 256>>>(adj);
    prep_kernel<<<dim3(32, 8, NB), 256>>>(feats);
    weff_mma<<<dim3(2, 4, NB * 3), 256>>>();
    corr2_kernel<<<3, 256>>>(adj, convw);

    const size_t SEC = (size_t)NB * CC * HW;
    dim3 grid(HW / 128, CC / 64, NB);
    layer_mma<0, 1><<<grid, 256>>>(
        out, 0,
        convb + 0 * CC, gamma + 0 * CC, beta + 0 * CC, mean + 0 * CC, var + 0 * CC);
    layer_mma<1, 0><<<grid, 256>>>(
        out + SEC, 1,
        convb + 1 * CC, gamma + 1 * CC, beta + 1 * CC, mean + 1 * CC, var + 1 * CC);
    layer_mma<0, -1><<<grid, 256>>>(
        out + 2 * SEC, 2,
        convb + 2 * CC, gamma + 2 * CC, beta + 2 * CC, mean + 2 * CC, var + 2 * CC);
}

// round 16
// speedup vs baseline: 2.0640x; 1.3527x over previous
#include <cuda_runtime.h>
#include <cuda_bf16.h>
#include <cstdint>

// FusionMarkovGNN — algebraically collapsed, all GEMMs on mma.sync (HMMA),
// launch-count minimized (5 graph nodes).
//   W_eff[n,l] = conv_w[l] @ mss[n] = wsum_l @ relu(adj_n) + rare exact
//   corrections (dense sign-pattern flags, applied inside weff_mma).
//   Per layer: y = relu(BN(W_eff[n,l] @ x + conv_b)).
// bf16 3-term split (hi*hi + hi*lo + lo*hi), fp32 accum, m16n8k16.
// Device globals referenced ONLY in device code (host-side refs are UB).

#define CC 256
#define SS 16
#define HW 1024
#define NB 4

typedef unsigned long long u64;
typedef uint32_t u32;

__device__ u32           g_wspack[3 * CC * CC];   // [l][o][a] packed split of wsum
__device__ u32           g_apack[NB * CC * CC];   // [n][b][a] packed split of relu(adj^T)
__device__ float         g_weff[NB * 3 * CC * CC];// [n][l][o][b]
__device__ u32           g_xpack[2][NB * HW * CC];// [buf][n][p][b]: (lo16<<16)|hi16
__device__ unsigned char g_flag[NB * SS * CC];    // dense: 0=relu,1=full,2=zero

// ---------------------------------------------------------------- helpers
__device__ __forceinline__ u32 smem_u32(const void* p) {
    u32 a;
    asm("{ .reg .u64 t; cvta.to.shared.u64 t, %1; cvt.u32.u64 %0, t; }" : "=r"(a) : "l"(p));
    return a;
}
__device__ __forceinline__ u32 pk2(float lo, float hi) {
    u32 r; asm("cvt.rn.bf16x2.f32 %0, %1, %2;" : "=r"(r) : "f"(hi), "f"(lo)); return r;
}
__device__ __forceinline__ void splt(float x, float& h, float& l) {
    __nv_bfloat16 bh = __float2bfloat16(x);
    h = __bfloat162float(bh);
    l = x - h;
}
__device__ __forceinline__ u32 packsplit(float y) {
    __nv_bfloat16 bh = __float2bfloat16(y);
    float hf = __bfloat162float(bh);
    __nv_bfloat16 bl = __float2bfloat16(y - hf);
    return ((u32)__bfloat16_as_ushort(bl) << 16) | (u32)__bfloat16_as_ushort(bh);
}
__device__ __forceinline__ void ldm4(u32& r0, u32& r1, u32& r2, u32& r3, u32 addr) {
    asm volatile("ldmatrix.sync.aligned.m8n8.x4.shared.b16 {%0,%1,%2,%3}, [%4];"
                 : "=r"(r0), "=r"(r1), "=r"(r2), "=r"(r3) : "r"(addr));
}
__device__ __forceinline__ void mma16816(float* c, const u32* a, const u32* b) {
    asm volatile(
        "mma.sync.aligned.m16n8k16.row.col.f32.bf16.bf16.f32 "
        "{%0,%1,%2,%3}, {%4,%5,%6,%7}, {%8,%9}, {%0,%1,%2,%3};"
        : "+f"(c[0]), "+f"(c[1]), "+f"(c[2]), "+f"(c[3])
        : "r"(a[0]), "r"(a[1]), "r"(a[2]), "r"(a[3]), "r"(b[0]), "r"(b[1]));
}

// ---------------------------------------------------------------- mega prep
// One kernel, 2112 blocks of 256 threads, dispatched on blockIdx.x:
//  [0,768):     wsum   -> g_wspack
//  [768,832):   detect -> g_flag (dense overwrite; deterministic)
//  [832,1088):  adjprep-> g_apack
//  [1088,2112): prep   -> g_xpack[0]
__global__ __launch_bounds__(256) void mega_prep(
    const float* __restrict__ feats,
    const float* __restrict__ adj,
    const float* __restrict__ w) {
    __shared__ float t[32][33];
    int bx = blockIdx.x;
    int tid = threadIdx.x;

    if (bx < 768) {
        int idx = bx * 256 + tid;
        int l  = idx >> 16;
        int oa = idx & 0xFFFF;
        int o = oa >> 8, a = oa & 255;
        const float* base = w + (size_t)l * CC * SS * CC + (size_t)o * (SS * CC) + a;
        float s = 0.0f;
#pragma unroll
        for (int k = 0; k < 16; k++) s += base[k * CC];
        g_wspack[idx] = packsplit(s);
    } else if (bx < 832) {
        int di = bx - 768;
        int n = di & 3, k = di >> 2;
        int b = tid;
        const float* m = adj + (size_t)n * CC * CC;
        bool anyp = false, allp = true;
#pragma unroll
        for (int i = 0; i < 16; i++) {
            float v = m[(size_t)(k * 16 + i) * CC + b];
            anyp = anyp || (v > 0.0f);
            allp = allp && (v > 0.0f);
        }
        g_flag[(n * SS + k) * CC + b] = allp ? 1 : (anyp ? 0 : 2);
    } else if (bx < 1088) {
        int ai = bx - 832;
        int n = ai >> 6, rem = ai & 63;
        int a0 = (rem >> 3) * 32, b0 = (rem & 7) * 32;
        int tx = tid & 31, ty = tid >> 5;
        const float* m = adj + (size_t)n * CC * CC;
#pragma unroll
        for (int i = 0; i < 4; i++) {
            int a = ty + i * 8;
            t[a][tx] = m[(size_t)(a0 + a) * CC + b0 + tx];
        }
        __syncthreads();
        u32* ap = g_apack + (size_t)n * CC * CC;
#pragma unroll
        for (int i = 0; i < 4; i++) {
            int b = ty + i * 8;
            ap[(size_t)(b0 + b) * CC + a0 + tx] = packsplit(fmaxf(t[tx][b], 0.0f));
        }
    } else {
        int pi = bx - 1088;
        int n = pi >> 8, rem = pi & 255;
        int p0 = (rem >> 3) * 32, b0 = (rem & 7) * 32;
        int tx = tid & 31, ty = tid >> 5;
        const float* f = feats + ((size_t)n * CC + b0) * HW + p0;
#pragma unroll
        for (int i = 0; i < 4; i++) {
            int b = ty + i * 8;
            t[b][tx] = f[(size_t)b * HW + tx];
        }
        __syncthreads();
        u32* xp = g_xpack[0] + ((size_t)n * HW + p0) * CC + b0;
#pragma unroll
        for (int i = 0; i < 4; i++) {
            int p = ty + i * 8;
            xp[(size_t)p * CC + tx] = packsplit(t[tx][p]);
        }
    }
}

// ---------------------------------------------------------------- shared smem layout
#define S_XHI 0
#define S_XLO 10240
#define S_WHI 20480
#define S_WLO 25600
#define S_DS  0
#define S_CSC 33792
#define S_CAD (33792 + 256)
#define S_TOT (33792 + 512)

// ---------------------------------------------------------------- weff via mma
// C[o][b] = wsum_l[o][a] @ relu(adj_n)^T[b][a]. Tile 128(o) x 64(b), K=256.
// Post-GEMM: exact corrections for full/zero flag columns (this block's
// output region only — disjoint across blocks, so plain global RMW is safe).
__global__ __launch_bounds__(256) void weff_mma(
    const float* __restrict__ adj, const float* __restrict__ convw) {
    __shared__ __align__(16) unsigned char sraw[S_TOT];
    __shared__ u32 clist[1024];
    __shared__ int ccnt;
    u32 sb = smem_u32(sraw);
    int tid = threadIdx.x;
    int wid = tid >> 5, lane = tid & 31;
    int wm = wid >> 1, wn = wid & 1;
    int m0 = wm * 32, n0 = wn * 32;

    int nl = blockIdx.z;
    int l = nl % 3, n = nl / 3;
    int o0 = blockIdx.x * 128;
    int b0 = blockIdx.y * 64;
    const u32* Ap = g_wspack + (size_t)l * CC * CC + (size_t)o0 * CC;
    const u32* Bp = g_apack  + (size_t)n * CC * CC + (size_t)b0 * CC;
    float* Cc = g_weff + (size_t)nl * CC * CC;

    int la = lane & 15, lb = (lane >> 4) & 1;
    int brr = (lane & 7) + ((lane & 16) ? 8 : 0);
    int bhalf = (lane >> 3) & 1;

    float acc[2][4][4] = {};

    int xp_p[4], xp_u[4];
#pragma unroll
    for (int i = 0; i < 4; i++) { int idx = tid + 256 * i; xp_p[i] = idx >> 3; xp_u[i] = idx & 7; }
    int wo[2], wu[2];
#pragma unroll
    for (int i = 0; i < 2; i++) { int idx = tid + 256 * i; wo[i] = idx >> 3; wu[i] = idx & 7; }

    uint4 gx[4], gw[2];
#pragma unroll
    for (int i = 0; i < 4; i++)
        gx[i] = *(const uint4*)(Ap + (size_t)xp_p[i] * CC + xp_u[i] * 4);
#pragma unroll
    for (int i = 0; i < 2; i++)
        gw[i] = *(const uint4*)(Bp + (size_t)wo[i] * CC + wu[i] * 4);

    for (int kc = 0; kc < 8; kc++) {
#pragma unroll
        for (int i = 0; i < 4; i++) {
            u32 v0 = gx[i].x, v1 = gx[i].y, v2 = gx[i].z, v3 = gx[i].w;
            *(uint2*)(sraw + S_XHI + xp_p[i] * 80 + xp_u[i] * 8) =
                make_uint2((v0 & 0xFFFFu) | (v1 << 16), (v2 & 0xFFFFu) | (v3 << 16));
            *(uint2*)(sraw + S_XLO + xp_p[i] * 80 + xp_u[i] * 8) =
                make_uint2((v0 >> 16) | (v1 & 0xFFFF0000u), (v2 >> 16) | (v3 & 0xFFFF0000u));
        }
#pragma unroll
        for (int i = 0; i < 2; i++) {
            u32 v0 = gw[i].x, v1 = gw[i].y, v2 = gw[i].z, v3 = gw[i].w;
            *(uint2*)(sraw + S_WHI + wo[i] * 80 + wu[i] * 8) =
                make_uint2((v0 & 0xFFFFu) | (v1 << 16), (v2 & 0xFFFFu) | (v3 << 16));
            *(uint2*)(sraw + S_WLO + wo[i] * 80 + wu[i] * 8) =
                make_uint2((v0 >> 16) | (v1 & 0xFFFF0000u), (v2 >> 16) | (v3 & 0xFFFF0000u));
        }
        __syncthreads();

        if (kc < 7) {
            int a0 = (kc + 1) * 32;
#pragma unroll
            for (int i = 0; i < 4; i++)
                gx[i] = *(const uint4*)(Ap + (size_t)xp_p[i] * CC + a0 + xp_u[i] * 4);
#pragma unroll
            for (int i = 0; i < 2; i++)
                gw[i] = *(const uint4*)(Bp + (size_t)wo[i] * CC + a0 + wu[i] * 4);
        }

#pragma unroll
        for (int ks = 0; ks < 2; ks++) {
            u32 ahi[2][4], alo[2][4];
#pragma unroll
            for (int mi = 0; mi < 2; mi++) {
                u32 off = (u32)((m0 + mi * 16 + la) * 80 + ks * 32 + lb * 16);
                ldm4(ahi[mi][0], ahi[mi][1], ahi[mi][2], ahi[mi][3], sb + S_XHI + off);
                ldm4(alo[mi][0], alo[mi][1], alo[mi][2], alo[mi][3], sb + S_XLO + off);
            }
            u32 bh[4][2], bl[4][2];
#pragma unroll
            for (int g = 0; g < 2; g++) {
                u32 off = (u32)((n0 + g * 16 + brr) * 80 + ks * 32 + bhalf * 16);
                u32 r0, r1, r2, r3;
                ldm4(r0, r1, r2, r3, sb + S_WHI + off);
                bh[g * 2][0] = r0; bh[g * 2][1] = r1;
                bh[g * 2 + 1][0] = r2; bh[g * 2 + 1][1] = r3;
                ldm4(r0, r1, r2, r3, sb + S_WLO + off);
                bl[g * 2][0] = r0; bl[g * 2][1] = r1;
                bl[g * 2 + 1][0] = r2; bl[g * 2 + 1][1] = r3;
            }
#pragma unroll
            for (int mi = 0; mi < 2; mi++)
#pragma unroll
                for (int ni = 0; ni < 4; ni++) {
                    mma16816(acc[mi][ni], ahi[mi], bh[ni]);
                    mma16816(acc[mi][ni], ahi[mi], bl[ni]);
                    mma16816(acc[mi][ni], alo[mi], bh[ni]);
                }
        }
        __syncthreads();
    }

    int pr = lane >> 2, oc = (lane & 3) * 2;
#pragma unroll
    for (int mi = 0; mi < 2; mi++)
#pragma unroll
        for (int ni = 0; ni < 4; ni++) {
            int o = o0 + m0 + mi * 16 + pr;
            int b = b0 + n0 + ni * 8 + oc;
            *(float2*)(Cc + (size_t)o * CC + b) =
                make_float2(acc[mi][ni][0], acc[mi][ni][1]);
            *(float2*)(Cc + (size_t)(o + 8) * CC + b) =
                make_float2(acc[mi][ni][2], acc[mi][ni][3]);
        }

    // ---- corrections (rare): scan dense flags for (n, all k, our b range)
    if (tid == 0) ccnt = 0;
    __syncthreads();
    for (int i = tid; i < SS * 64; i += 256) {
        int k = i >> 6, bb = b0 + (i & 63);
        unsigned char st = g_flag[(n * SS + k) * CC + bb];
        if (st) { int idx = atomicAdd(&ccnt, 1); clist[idx] = (u32)((k << 10) | (bb << 2) | st); }
    }
    __syncthreads();
    int cnt = ccnt;
    for (int e = 0; e < cnt; e++) {
        u32 ent = clist[e];
        int k = ent >> 10, bb = (ent >> 2) & 0xFF, st = ent & 3;
        if (tid < 128) {
            int o = o0 + tid;
            const float* wrow = convw + (size_t)l * CC * SS * CC + (size_t)o * (SS * CC) + k * CC;
            const float* m = adj + (size_t)n * CC * CC;
            float s = 0.0f;
            if (st == 1) {
                for (int a = 0; a < CC; a++) s = fmaf(wrow[a], fminf(m[(size_t)a * CC + bb], 0.0f), s);
            } else {
                for (int a = 0; a < CC; a++) s = fmaf(-wrow[a], fmaxf(m[(size_t)a * CC + bb], 0.0f), s);
            }
            Cc[(size_t)o * CC + bb] += s;
        }
    }
}

// ---------------------------------------------------------------- mma.sync layer
// Block tile: 128 (p) x 64 (o), K = 256 in 8 chunks of 32. 256 threads.
template <int IN_BUF, int OUT_BUF>
__global__ __launch_bounds__(256) void layer_mma(
    float* __restrict__ Y,
    int l,
    const float* __restrict__ cb_, const float* __restrict__ gamma_,
    const float* __restrict__ beta_, const float* __restrict__ mean_,
    const float* __restrict__ var_) {
    __shared__ __align__(16) unsigned char sraw[S_TOT];
    u32 sb = smem_u32(sraw);
    int tid = threadIdx.x;
    int wid = tid >> 5, lane = tid & 31;
    int wm = wid >> 1, wn = wid & 1;
    int m0 = wm * 32, n0 = wn * 32;

    int n = blockIdx.z;
    int pcol0 = blockIdx.x * 128;
    int o0 = blockIdx.y * 64;
    const u32* Xp = g_xpack[IN_BUF] + ((size_t)n * HW + pcol0) * CC;
    const float* Wp = g_weff + (size_t)(n * 3 + l) * CC * CC + (size_t)o0 * CC;

    int la = lane & 15, lb = (lane >> 4) & 1;
    int brr = (lane & 7) + ((lane & 16) ? 8 : 0);
    int bhalf = (lane >> 3) & 1;

    float acc[2][4][4] = {};

    int xp_p[4], xp_u[4];
#pragma unroll
    for (int i = 0; i < 4; i++) { int idx = tid + 256 * i; xp_p[i] = idx >> 3; xp_u[i] = idx & 7; }
    int wo[2], wu[2];
#pragma unroll
    for (int i = 0; i < 2; i++) { int idx = tid + 256 * i; wo[i] = idx >> 3; wu[i] = idx & 7; }

    uint4 gx[4];
    float4 gw[2];
#pragma unroll
    for (int i = 0; i < 4; i++)
        gx[i] = *(const uint4*)(Xp + (size_t)xp_p[i] * CC + xp_u[i] * 4);
#pragma unroll
    for (int i = 0; i < 2; i++)
        gw[i] = *(const float4*)(Wp + (size_t)wo[i] * CC + wu[i] * 4);

    for (int kc = 0; kc < 8; kc++) {
#pragma unroll
        for (int i = 0; i < 4; i++) {
            u32 v0 = gx[i].x, v1 = gx[i].y, v2 = gx[i].z, v3 = gx[i].w;
            *(uint2*)(sraw + S_XHI + xp_p[i] * 80 + xp_u[i] * 8) =
                make_uint2((v0 & 0xFFFFu) | (v1 << 16), (v2 & 0xFFFFu) | (v3 << 16));
            *(uint2*)(sraw + S_XLO + xp_p[i] * 80 + xp_u[i] * 8) =
                make_uint2((v0 >> 16) | (v1 & 0xFFFF0000u), (v2 >> 16) | (v3 & 0xFFFF0000u));
        }
#pragma unroll
        for (int i = 0; i < 2; i++) {
            float h0, h1, h2, h3, l0, l1, l2, l3;
            splt(gw[i].x, h0, l0); splt(gw[i].y, h1, l1);
            splt(gw[i].z, h2, l2); splt(gw[i].w, h3, l3);
            *(uint2*)(sraw + S_WHI + wo[i] * 80 + wu[i] * 8) = make_uint2(pk2(h0, h1), pk2(h2, h3));
            *(uint2*)(sraw + S_WLO + wo[i] * 80 + wu[i] * 8) = make_uint2(pk2(l0, l1), pk2(l2, l3));
        }
        __syncthreads();

        if (kc < 7) {
            int b0 = (kc + 1) * 32;
#pragma unroll
            for (int i = 0; i < 4; i++)
                gx[i] = *(const uint4*)(Xp + (size_t)xp_p[i] * CC + b0 + xp_u[i] * 4);
#pragma unroll
            for (int i = 0; i < 2; i++)
                gw[i] = *(const float4*)(Wp + (size_t)wo[i] * CC + b0 + wu[i] * 4);
        }

#pragma unroll
        for (int ks = 0; ks < 2; ks++) {
            u32 ahi[2][4], alo[2][4];
#pragma unroll
            for (int mi = 0; mi < 2; mi++) {
                u32 off = (u32)((m0 + mi * 16 + la) * 80 + ks * 32 + lb * 16);
                ldm4(ahi[mi][0], ahi[mi][1], ahi[mi][2], ahi[mi][3], sb + S_XHI + off);
                ldm4(alo[mi][0], alo[mi][1], alo[mi][2], alo[mi][3], sb + S_XLO + off);
            }
            u32 bh[4][2], bl[4][2];
#pragma unroll
            for (int g = 0; g < 2; g++) {
                u32 off = (u32)((n0 + g * 16 + brr) * 80 + ks * 32 + bhalf * 16);
                u32 r0, r1, r2, r3;
                ldm4(r0, r1, r2, r3, sb + S_WHI + off);
                bh[g * 2][0] = r0; bh[g * 2][1] = r1;
                bh[g * 2 + 1][0] = r2; bh[g * 2 + 1][1] = r3;
                ldm4(r0, r1, r2, r3, sb + S_WLO + off);
                bl[g * 2][0] = r0; bl[g * 2][1] = r1;
                bl[g * 2 + 1][0] = r2; bl[g * 2 + 1][1] = r3;
            }
#pragma unroll
            for (int mi = 0; mi < 2; mi++)
#pragma unroll
                for (int ni = 0; ni < 4; ni++) {
                    mma16816(acc[mi][ni], ahi[mi], bh[ni]);
                    mma16816(acc[mi][ni], ahi[mi], bl[ni]);
                    mma16816(acc[mi][ni], alo[mi], bh[ni]);
                }
        }
        __syncthreads();
    }

    // ---- epilogue
    float* Ds  = (float*)(sraw + S_DS);
    float* csc = (float*)(sraw + S_CSC);
    float* cad = (float*)(sraw + S_CAD);
    if (tid < 64) {
        int o = o0 + tid;
        float sc = gamma_[o] * rsqrtf(var_[o] + 1e-5f);
        csc[tid] = sc;
        cad[tid] = (cb_[o] - mean_[o]) * sc + beta_[o];
    }
    int pr = lane >> 2, oc = (lane & 3) * 2;
#pragma unroll
    for (int mi = 0; mi < 2; mi++)
#pragma unroll
        for (int ni = 0; ni < 4; ni++) {
            int p = m0 + mi * 16 + pr;
            int o = n0 + ni * 8 + oc;
            *(float2*)&Ds[p * 66 + o]       = make_float2(acc[mi][ni][0], acc[mi][ni][1]);
            *(float2*)&Ds[(p + 8) * 66 + o] = make_float2(acc[mi][ni][2], acc[mi][ni][3]);
        }
    __syncthreads();

    float* Yn = Y + (size_t)n * CC * HW;
    for (int idx = tid; idx < 64 * 128; idx += 256) {
        int o = idx >> 7, p = idx & 127;
        float v = fmaxf(fmaf(Ds[p * 66 + o], csc[o], cad[o]), 0.0f);
        Yn[(size_t)(o0 + o) * HW + pcol0 + p] = v;
    }
    if (OUT_BUF >= 0) {
        u32* Xo = g_xpack[OUT_BUF < 0 ? 0 : OUT_BUF] + ((size_t)n * HW + pcol0) * CC + o0;
        for (int idx = tid; idx < 128 * 64; idx += 256) {
            int p = idx >> 6, o = idx & 63;
            float v = fmaxf(fmaf(Ds[p * 66 + o], csc[o], cad[o]), 0.0f);
            Xo[(size_t)p * CC + o] = packsplit(v);
        }
    }
}

// ---------------------------------------------------------------- launch
extern "C" void kernel_launch(void* const* d_in, const int* in_sizes, int n_in,
                              void* d_out, int out_size) {
    (void)in_sizes; (void)n_in; (void)out_size;
    const float* feats = (const float*)d_in[0];  // [4,256,32,32]
    const float* adj   = (const float*)d_in[1];  // [4,256,256]
    const float* convw = (const float*)d_in[2];  // [3,256,4096]
    const float* convb = (const float*)d_in[3];  // [3,256]
    const float* gamma = (const float*)d_in[4];
    const float* beta  = (const float*)d_in[5];
    const float* mean  = (const float*)d_in[6];
    const float* var   = (const float*)d_in[7];
    float* out = (float*)d_out;                  // [3,4,256,32,32]

    mega_prep<<<2112, 256>>>(feats, adj, convw);
    weff_mma<<<dim3(2, 4, NB * 3), 256>>>(adj, convw);

    const size_t SEC = (size_t)NB * CC * HW;
    dim3 grid(HW / 128, CC / 64, NB);
    layer_mma<0, 1><<<grid, 256>>>(
        out, 0,
        convb + 0 * CC, gamma + 0 * CC, beta + 0 * CC, mean + 0 * CC, var + 0 * CC);
    layer_mma<1, 0><<<grid, 256>>>(
        out + SEC, 1,
        convb + 1 * CC, gamma + 1 * CC, beta + 1 * CC, mean + 1 * CC, var + 1 * CC);
    layer_mma<0, -1><<<grid, 256>>>(
        out + 2 * SEC, 2,
        convb + 2 * CC, gamma + 2 * CC, beta + 2 * CC, mean + 2 * CC, var + 2 * CC);
}